// round 6
// baseline (speedup 1.0000x reference)
#include <cuda_runtime.h>

typedef unsigned long long ull;

constexpr int Bn = 8, Sn = 2048, Pn = 1024, ITERS = 50;
constexpr int CPB = 32, GRID = Bn * CPB, NT = 256;

constexpr float SQI     = 12.011224081528898f;   // sqrt((1/eps)*log2 e)
constexpr float IL2     = 144.26950408889634f;
constexpr float LOG2S   = 11.0f;
constexpr float NEG_BIG = -1.4426950408889634e9f;
constexpr float TH      = 40.0f;

// smem float offsets (flat buffer; sort keys overlay coord regions)
constexpr int O_X1 = 0, O_X2 = Sn, O_QX = 2 * Sn;          // X: 2SQI*x
constexpr int O_Y1 = 3 * Sn, O_Y2 = 3 * Sn + Pn, O_QY = 3 * Sn + 2 * Pn;
constexpr int O_MX = 3 * Sn + 3 * Pn;                      // 256
constexpr int O_AC = O_MX + 256;                           // 256
constexpr int O_MS = O_AC + 256;                           // l2b32,cnt32,swm8,sb4,sred8
constexpr int SMT  = O_MS + 96;

__device__ float g_fs[Bn * Sn], g_gs[Bn * Pn];
__device__ float g_fbm[Bn * CPB], g_gbm[Bn * CPB];
__device__ float g_part[GRID];
__device__ unsigned g_cnt[Bn];
__device__ volatile unsigned g_sns[Bn];
__device__ unsigned g_gcnt;

__device__ __forceinline__ float ex2(float x) { float r; asm("ex2.approx.f32 %0, %1;" : "=f"(r) : "f"(x)); return r; }
__device__ __forceinline__ float lg2(float x) { float r; asm("lg2.approx.f32 %0, %1;" : "=f"(r) : "f"(x)); return r; }
__device__ __forceinline__ ull pk(float lo, float hi) { ull r; asm("mov.b64 %0, {%1, %2};" : "=l"(r) : "f"(lo), "f"(hi)); return r; }
__device__ __forceinline__ void upk(ull p, float& a, float& b) { asm("mov.b64 {%0, %1}, %2;" : "=f"(a), "=f"(b) : "l"(p)); }
__device__ __forceinline__ ull add2(ull a, ull b) { ull r; asm("add.rn.f32x2 %0, %1, %2;" : "=l"(r) : "l"(a), "l"(b)); return r; }
__device__ __forceinline__ ull fma2(ull a, ull b, ull c) { ull r; asm("fma.rn.f32x2 %0, %1, %2, %3;" : "=l"(r) : "l"(a), "l"(b), "l"(c)); return r; }
__device__ __forceinline__ float hsum2(ull p) { float a, b; upk(p, a, b); return a + b; }
__device__ __forceinline__ float warp_sum(float a) {
    #pragma unroll
    for (int o = 16; o; o >>= 1) a += __shfl_xor_sync(0xffffffffu, a, o);
    return a;
}
__device__ __forceinline__ float warp_max(float a) {
    #pragma unroll
    for (int o = 16; o; o >>= 1) a = fmaxf(a, __shfl_xor_sync(0xffffffffu, a, o));
    return a;
}
__device__ __forceinline__ float warp_min(float a) {
    #pragma unroll
    for (int o = 16; o; o >>= 1) a = fminf(a, __shfl_xor_sync(0xffffffffu, a, o));
    return a;
}
__device__ __forceinline__ unsigned fkey(float f) {
    unsigned u = __float_as_uint(f);
    return (u & 0x80000000u) ? ~u : (u | 0x80000000u);
}
__device__ void bitonic(ull* k, int n) {
    for (int sz = 2; sz <= n; sz <<= 1)
        for (int st = sz >> 1; st > 0; st >>= 1) {
            __syncthreads();
            for (int i = threadIdx.x; i < n; i += NT) {
                int j = i ^ st;
                if (j > i) {
                    bool up = ((i & sz) == 0);
                    ull a = k[i], b = k[j];
                    if ((a > b) == up) { k[i] = b; k[j] = a; }
                }
            }
        }
    __syncthreads();
}
__device__ __forceinline__ int lbound(const float* a, int n, float key) {
    int lo = 0, hi = n;
    while (lo < hi) { int mid = (lo + hi) >> 1; if (a[mid] < key) lo = mid + 1; else hi = mid; }
    return lo;
}
__device__ __forceinline__ void online8(const ull* t, float& m, ull& acc) {
    float px[8];
    #pragma unroll
    for (int j = 0; j < 8; j++) { float a, b; upk(t[j], a, b); px[j] = fmaxf(a, b); }
    float mn = fmaxf(fmaxf(fmaxf(px[0], px[1]), fmaxf(px[2], px[3])),
                     fmaxf(fmaxf(px[4], px[5]), fmaxf(px[6], px[7])));
    mn = fmaxf(m, mn);
    float r = ex2(m - mn);
    ull rm = pk(-mn, -mn), e[8];
    #pragma unroll
    for (int j = 0; j < 8; j++) { float a, b; upk(add2(t[j], rm), a, b); e[j] = pk(ex2(a), ex2(b)); }
    ull s = add2(add2(add2(e[0], e[1]), add2(e[2], e[3])),
                 add2(add2(e[4], e[5]), add2(e[6], e[7])));
    acc = fma2(acc, pk(r, r), s);
    m = mn;
}
__device__ __forceinline__ void bat_bar(int b, unsigned& ls) {
    ls ^= 1u;
    __threadfence();
    __syncthreads();
    if (threadIdx.x == 0) {
        unsigned old = atomicAdd(&g_cnt[b], 1);
        if (old == CPB - 1) { g_cnt[b] = 0; __threadfence(); g_sns[b] = ls; }
        else { while (g_sns[b] != ls) { } }
        __threadfence();
    }
    __syncthreads();
}

__global__ void __launch_bounds__(NT, 2) sinkhorn_kernel(
    const float* __restrict__ pred, const int* __restrict__ labels,
    const float* __restrict__ pos, float* __restrict__ out)
{
    __shared__ __align__(16) float SM[SMT];
    float* X1 = SM + O_X1;  float* X2 = SM + O_X2;  float* Qx = SM + O_QX;
    float* Y1 = SM + O_Y1;  float* Y2 = SM + O_Y2;  float* Qy = SM + O_QY;
    float* smx = SM + O_MX; float* sac = SM + O_AC;
    float* s_l2b = SM + O_MS;            int* s_cnt = (int*)(SM + O_MS + 32);
    float* swm = SM + O_MS + 64;         float* sb = SM + O_MS + 72;
    float* sred = SM + O_MS + 76;

    int tid = threadIdx.x, w = tid >> 5, lane = tid & 31;
    int b = blockIdx.x >> 5, cb = blockIdx.x & 31;
    int col0 = cb * 32;

    // ---- sort both sets by coord0 (keys overlay coord regions) ----
    ull* xk = (ull*)(SM + O_X1);   // spans X1,X2 (16KB)
    ull* yk = (ull*)(SM + O_Y1);   // spans Y1,Y2 (8KB)
    const float2* pr2 = (const float2*)pred;
    const float2* po2 = (const float2*)pos;
    for (int i = tid; i < Pn; i += NT) yk[i] = ((ull)fkey(po2[b * Pn + i].x) << 32) | (unsigned)i;
    for (int i = tid; i < Sn; i += NT) xk[i] = ((ull)fkey(pr2[b * Sn + i].x) << 32) | (unsigned)i;
    bitonic(yk, Pn);
    bitonic(xk, Sn);
    ull myy[4], myx[8];
    #pragma unroll
    for (int t = 0; t < 4; t++) myy[t] = yk[tid + t * NT];
    #pragma unroll
    for (int t = 0; t < 8; t++) myx[t] = xk[tid + t * NT];
    __syncthreads();
    int* rk = (int*)(SM + O_QY);   // rank map (transient in Qy region)
    #pragma unroll
    for (int t = 0; t < 4; t++) {
        int i = tid + t * NT, idx = (int)(myy[t] & 0xFFFFFFFFu);
        float2 p = po2[b * Pn + idx];
        Y1[i] = SQI * p.x; Y2[i] = SQI * p.y; rk[idx] = i;
    }
    #pragma unroll
    for (int t = 0; t < 8; t++) {
        int i = tid + t * NT, idx = (int)(myx[t] & 0xFFFFFFFFu);
        float2 p = pr2[b * Sn + idx];
        X1[i] = 2.f * SQI * p.x; X2[i] = 2.f * SQI * p.y;
    }
    if (tid < 32) s_cnt[tid] = 0;
    __syncthreads();
    for (int s = tid; s < Sn; s += NT) {
        int rr = rk[labels[b * Sn + s]] - col0;
        if ((unsigned)rr < 32u) atomicAdd(&s_cnt[rr], 1);
    }
    __syncthreads();
    if (tid < 32) {
        int c = s_cnt[tid];
        s_l2b[tid] = (c > 0) ? lg2((float)c * (1.f / (float)Sn)) : NEG_BIG;
    }
    for (int i = tid; i < Pn; i += NT) Qy[i] = -(Y1[i] * Y1[i] + Y2[i] * Y2[i]);  // gs=0
    if (tid == 0) sb[1] = 0.f;
    unsigned ls = g_sns[b];
    __syncthreads();

    // per-lane constants: f rows (4-warp groups share 32 sorted rows), g cols
    int fg = w >> 2, fq = w & 3;
    int frow = cb * 32 + fg * 1024 + lane;
    float X1s = X1[frow], X2s = X2[frow];
    float xq = 0.5f * X1s;                             // SQI units
    float xn = 0.25f * (X1s * X1s + X2s * X2s);        // IL2*|x|^2
    ull X1p = pk(X1s, X1s), X2p = pk(X2s, X2s);
    int fpos = lbound(Y1, Pn, xq);
    int fj0 = min(max(fpos - 8, 0), Pn - 16);

    float Y1s = Y1[col0 + lane], Y2s = Y2[col0 + lane];
    float yn = Y1s * Y1s + Y2s * Y2s;
    ull Y1p = pk(Y1s, Y1s), Y2p = pk(Y2s, Y2s);
    int gpos = lbound(X1, Sn, 2.f * Y1s);
    int gj0 = min(max(gpos - 8, 0), Sn - 16);

    for (int it = 0; it < ITERS; ++it) {
        float gsm = sb[1];
        // ---- f half: t = X*Y + Qy = (gs - C*IL2) + xn ----
        {
            float LB = -3e38f;
            #pragma unroll
            for (int j = 0; j < 16; j++)
                LB = fmaxf(LB, fmaf(X1s, Y1[fj0 + j], fmaf(X2s, Y2[fj0 + j], Qy[fj0 + j])));
            float h = sqrtf(gsm - LB + xn + TH);
            float lo = warp_min(xq - h), hi = warp_max(xq + h);
            int c0 = lbound(Y1, Pn, lo) >> 4;
            int c1 = min(Pn >> 4, (lbound(Y1, Pn, hi) >> 4) + 1);
            float m = -3e38f; ull acc = 0ull;
            for (int c = c0 + fq; c < c1; c += 4) {
                const float *p1 = Y1 + c * 16, *p2 = Y2 + c * 16, *pq = Qy + c * 16;
                ull t[8];
                #pragma unroll
                for (int j = 0; j < 8; j++)
                    t[j] = fma2(X1p, *(const ull*)(p1 + 2 * j),
                           fma2(X2p, *(const ull*)(p2 + 2 * j), *(const ull*)(pq + 2 * j)));
                online8(t, m, acc);
            }
            smx[w * 32 + lane] = m; sac[w * 32 + lane] = hsum2(acc);
        }
        __syncthreads();
        if (tid < 64) {
            int g = tid >> 5, r = tid & 31;
            float M = -3e38f, A = 0.f;
            #pragma unroll
            for (int i = 0; i < 4; i++) M = fmaxf(M, smx[(g * 4 + i) * 32 + r]);
            #pragma unroll
            for (int i = 0; i < 4; i++) A += sac[(g * 4 + i) * 32 + r] * ex2(smx[(g * 4 + i) * 32 + r] - M);
            int row = cb * 32 + g * 1024 + r;
            float xnr = 0.25f * (X1[row] * X1[row] + X2[row] * X2[row]);
            float fv = -LOG2S - M - lg2(A) + xnr;
            g_fs[b * Sn + row] = fv;
            float bm = warp_max(fv);
            if (r == 0) swm[g] = bm;
        }
        __syncthreads();
        if (tid == 0) g_fbm[b * CPB + cb] = fmaxf(swm[0], swm[1]);
        bat_bar(b, ls);
        for (int i = tid; i < Sn; i += NT)
            Qx[i] = __ldcg(&g_fs[b * Sn + i]) - 0.25f * (X1[i] * X1[i] + X2[i] * X2[i]);
        if (tid < 32) {
            float v = warp_max(__ldcg(&g_fbm[b * CPB + tid]));
            if (tid == 0) sb[0] = v;
        }
        __syncthreads();
        float fsm = sb[0];

        // ---- g half: t = Y*X + Qx = (fs - C*IL2) + yn ----
        {
            float LB = -3e38f;
            #pragma unroll
            for (int j = 0; j < 16; j++)
                LB = fmaxf(LB, fmaf(Y1s, X1[gj0 + j], fmaf(Y2s, X2[gj0 + j], Qx[gj0 + j])));
            float h = sqrtf(fsm - LB + yn + TH);
            float lo = warp_min(2.f * (Y1s - h)), hi = warp_max(2.f * (Y1s + h));
            int c0 = lbound(X1, Sn, lo) >> 4;
            int c1 = min(Sn >> 4, (lbound(X1, Sn, hi) >> 4) + 1);
            float m = -3e38f; ull acc = 0ull;
            for (int c = c0 + w; c < c1; c += 8) {
                const float *p1 = X1 + c * 16, *p2 = X2 + c * 16, *pq = Qx + c * 16;
                ull t[8];
                #pragma unroll
                for (int j = 0; j < 8; j++)
                    t[j] = fma2(Y1p, *(const ull*)(p1 + 2 * j),
                           fma2(Y2p, *(const ull*)(p2 + 2 * j), *(const ull*)(pq + 2 * j)));
                online8(t, m, acc);
            }
            smx[w * 32 + lane] = m; sac[w * 32 + lane] = hsum2(acc);
        }
        __syncthreads();
        if (tid < 32) {
            float M = -3e38f, A = 0.f;
            #pragma unroll
            for (int i = 0; i < 8; i++) M = fmaxf(M, smx[i * 32 + tid]);
            #pragma unroll
            for (int i = 0; i < 8; i++) A += sac[i * 32 + tid] * ex2(smx[i * 32 + tid] - M);
            float ynr = Y1[col0 + tid] * Y1[col0 + tid] + Y2[col0 + tid] * Y2[col0 + tid];
            float gv = s_l2b[tid] - M - lg2(A) + ynr;
            g_gs[b * Pn + col0 + tid] = gv;
            float bm = warp_max(gv);
            if (tid == 0) g_gbm[b * CPB + cb] = bm;
        }
        bat_bar(b, ls);
        for (int i = tid; i < Pn; i += NT)
            Qy[i] = __ldcg(&g_gs[b * Pn + i]) - (Y1[i] * Y1[i] + Y2[i] * Y2[i]);
        if (tid < 32) {
            float v = warp_max(__ldcg(&g_gbm[b * CPB + tid]));
            if (tid == 0) sb[1] = v;
        }
        __syncthreads();
    }

    // ---- final transport distance: sum exp2(t + Qx_row) * (Qy + yn + xn - t) ----
    {
        float gsm = sb[1];
        float LB = -3e38f;
        #pragma unroll
        for (int j = 0; j < 16; j++)
            LB = fmaxf(LB, fmaf(X1s, Y1[fj0 + j], fmaf(X2s, Y2[fj0 + j], Qy[fj0 + j])));
        float h = sqrtf(gsm - LB + xn + TH);
        float lo = warp_min(xq - h), hi = warp_max(xq + h);
        int c0 = lbound(Y1, Pn, lo) >> 4;
        int c1 = min(Pn >> 4, (lbound(Y1, Pn, hi) >> 4) + 1);
        float q0 = Qx[frow];
        float acc = 0.f;
        for (int c = c0 + fq; c < c1; c += 4) {
            const float *p1 = Y1 + c * 16, *p2 = Y2 + c * 16, *pq = Qy + c * 16;
            #pragma unroll
            for (int j = 0; j < 8; j++) {
                ull y1 = *(const ull*)(p1 + 2 * j);
                ull y2 = *(const ull*)(p2 + 2 * j);
                ull qp = *(const ull*)(pq + 2 * j);
                ull t = fma2(X1p, y1, fma2(X2p, y2, qp));
                float ta, tb, qa, qb, y1a, y1b, y2a, y2b;
                upk(t, ta, tb); upk(qp, qa, qb); upk(y1, y1a, y1b); upk(y2, y2a, y2b);
                float ca = qa + (y1a * y1a + y2a * y2a) + xn - ta;   // C*IL2
                float cbv = qb + (y1b * y1b + y2b * y2b) + xn - tb;
                acc = fmaf(ex2(ta + q0), ca, acc);
                acc = fmaf(ex2(tb + q0), cbv, acc);
            }
        }
        acc = warp_sum(acc);
        if (lane == 0) sred[w] = acc;
    }
    __syncthreads();
    if (tid == 0) {
        float s = 0.f;
        #pragma unroll
        for (int i = 0; i < 8; i++) s += sred[i];
        g_part[blockIdx.x] = s;
    }

    // ---- grid-wide deterministic reduce ----
    __threadfence();
    __syncthreads();
    if (blockIdx.x == 0) {
        if (tid == 0) {
            atomicAdd(&g_gcnt, 1u);
            while (*((volatile unsigned*)&g_gcnt) < (unsigned)GRID) { }
            __threadfence();
        }
        __syncthreads();
        smx[tid] = __ldcg(&g_part[tid]);
        __syncthreads();
        #pragma unroll
        for (int o = 128; o; o >>= 1) {
            if (tid < o) smx[tid] += smx[tid + o];
            __syncthreads();
        }
        if (tid == 0) {
            out[0] = smx[0] * (1.f / (IL2 * (float)Bn));
            g_gcnt = 0;
        }
    } else {
        if (tid == 0) atomicAdd(&g_gcnt, 1u);
    }
}

extern "C" void kernel_launch(void* const* d_in, const int* in_sizes, int n_in,
                              void* d_out, int out_size) {
    const float* pred   = (const float*)d_in[0];
    const int*   labels = (const int*)d_in[1];
    const float* pos    = (const float*)d_in[2];
    float*       out    = (float*)d_out;

    sinkhorn_kernel<<<GRID, NT>>>(pred, labels, pos, out);
}

// round 7
// speedup vs baseline: 1.0743x; 1.0743x over previous
#include <cuda_runtime.h>
typedef unsigned long long ull;

constexpr int Bn = 8, Sn = 2048, Pn = 1024, ITERS = 50;
constexpr int CPB = 32, GRID = Bn * CPB, NT = 256;
constexpr int NCY = Pn / 16, NCX = Sn / 16;   // 64, 128 chunks

constexpr float SQI     = 12.011224081528898f;   // sqrt((1/eps)*log2 e)
constexpr float IL2     = 144.26950408889634f;
constexpr float LOG2S   = 11.0f;
constexpr float NEG_BIG = -1.4426950408889634e9f;
constexpr float TH      = 30.0f;

// smem float offsets
constexpr int O_X1 = 0, O_X2 = Sn, O_QX = 2 * Sn;
constexpr int O_Y1 = 3 * Sn, O_Y2 = 3 * Sn + Pn, O_QY = 3 * Sn + 2 * Pn;
constexpr int O_MX = 3 * Sn + 3 * Pn;    // [8][64]
constexpr int O_AC = O_MX + 512;         // [8][64]
constexpr int O_UY = O_AC + 512;         // 64  max gs per Y-chunk
constexpr int O_UX = O_UY + 64;          // 128 max fs per X-chunk
constexpr int O_YL = O_UX + 128;         // 64  chunk y1 lo (SQI units)
constexpr int O_YH = O_YL + 64;
constexpr int O_XL = O_YH + 64;          // 128 chunk x1 lo (SQI units)
constexpr int O_XH = O_XL + 128;
constexpr int O_MS = O_XH + 128;         // l2b32, cnt32, sred8
constexpr int SMT  = O_MS + 72;

__device__ float g_fs[Bn * Sn], g_gs[Bn * Pn];
__device__ float g_part[GRID];
__device__ unsigned g_cnt[Bn];
__device__ volatile unsigned g_sns[Bn];
__device__ unsigned g_gcnt;

__device__ __forceinline__ float ex2(float x) { float r; asm("ex2.approx.f32 %0, %1;" : "=f"(r) : "f"(x)); return r; }
__device__ __forceinline__ float lg2(float x) { float r; asm("lg2.approx.f32 %0, %1;" : "=f"(r) : "f"(x)); return r; }
__device__ __forceinline__ ull pk(float lo, float hi) { ull r; asm("mov.b64 %0, {%1, %2};" : "=l"(r) : "f"(lo), "f"(hi)); return r; }
__device__ __forceinline__ void upk(ull p, float& a, float& b) { asm("mov.b64 {%0, %1}, %2;" : "=f"(a), "=f"(b) : "l"(p)); }
__device__ __forceinline__ ull add2(ull a, ull b) { ull r; asm("add.rn.f32x2 %0, %1, %2;" : "=l"(r) : "l"(a), "l"(b)); return r; }
__device__ __forceinline__ ull fma2(ull a, ull b, ull c) { ull r; asm("fma.rn.f32x2 %0, %1, %2, %3;" : "=l"(r) : "l"(a), "l"(b), "l"(c)); return r; }
__device__ __forceinline__ float hsum2(ull p) { float a, b; upk(p, a, b); return a + b; }
__device__ __forceinline__ float warp_sum(float a) {
    #pragma unroll
    for (int o = 16; o; o >>= 1) a += __shfl_xor_sync(0xffffffffu, a, o);
    return a;
}
__device__ __forceinline__ float warp_min(float a) {
    #pragma unroll
    for (int o = 16; o; o >>= 1) a = fminf(a, __shfl_xor_sync(0xffffffffu, a, o));
    return a;
}
__device__ __forceinline__ unsigned fkey(float f) {
    unsigned u = __float_as_uint(f);
    return (u & 0x80000000u) ? ~u : (u | 0x80000000u);
}
__device__ void bitonic(ull* k, int n) {
    for (int sz = 2; sz <= n; sz <<= 1)
        for (int st = sz >> 1; st > 0; st >>= 1) {
            __syncthreads();
            for (int i = threadIdx.x; i < n; i += NT) {
                int j = i ^ st;
                if (j > i) {
                    bool up = ((i & sz) == 0);
                    ull a = k[i], b = k[j];
                    if ((a > b) == up) { k[i] = b; k[j] = a; }
                }
            }
        }
    __syncthreads();
}
__device__ __forceinline__ int lbound(const float* a, int n, float key) {
    int lo = 0, hi = n;
    while (lo < hi) { int mid = (lo + hi) >> 1; if (a[mid] < key) lo = mid + 1; else hi = mid; }
    return lo;
}
__device__ __forceinline__ void online8(const ull* t, float& m, ull& acc) {
    float px[8];
    #pragma unroll
    for (int j = 0; j < 8; j++) { float a, b; upk(t[j], a, b); px[j] = fmaxf(a, b); }
    float mn = fmaxf(fmaxf(fmaxf(px[0], px[1]), fmaxf(px[2], px[3])),
                     fmaxf(fmaxf(px[4], px[5]), fmaxf(px[6], px[7])));
    mn = fmaxf(m, mn);
    float r = ex2(m - mn);
    ull rm = pk(-mn, -mn), e[8];
    #pragma unroll
    for (int j = 0; j < 8; j++) { float a, b; upk(add2(t[j], rm), a, b); e[j] = pk(ex2(a), ex2(b)); }
    ull s = add2(add2(add2(e[0], e[1]), add2(e[2], e[3])),
                 add2(add2(e[4], e[5]), add2(e[6], e[7])));
    acc = fma2(acc, pk(r, r), s);
    m = mn;
}
__device__ __forceinline__ void bat_bar(int b, unsigned& ls) {
    ls ^= 1u;
    __threadfence();
    __syncthreads();
    if (threadIdx.x == 0) {
        unsigned old = atomicAdd(&g_cnt[b], 1);
        if (old == CPB - 1) { g_cnt[b] = 0; __threadfence(); g_sns[b] = ls; }
        else { while (g_sns[b] != ls) { } }
        __threadfence();
    }
    __syncthreads();
}
// chunk range via ballot: keep chunk c iff U[c] - d^2 >= thr, d = gap to CTA interval
__device__ __forceinline__ void crange(const float* U, const float* cl, const float* ch,
                                       int nc, float wlo, float whi, float thr,
                                       int lane, int& lo, int& hi) {
    unsigned bb[4]; int nb = nc >> 5;
    #pragma unroll
    for (int q = 0; q < 4; q++) {
        if (q < nb) {
            int c = lane + q * 32;
            float d = fmaxf(0.f, fmaxf(cl[c] - whi, wlo - ch[c]));
            bb[q] = __ballot_sync(0xffffffffu, U[c] - d * d >= thr);
        } else bb[q] = 0u;
    }
    lo = 0; hi = nc - 1;
    #pragma unroll
    for (int q = 3; q >= 0; q--) if (bb[q]) lo = q * 32 + __ffs(bb[q]) - 1;
    #pragma unroll
    for (int q = 0; q < 4; q++) if (bb[q]) hi = q * 32 + 31 - __clz(bb[q]);
}

__global__ void __launch_bounds__(NT, 2) sinkhorn_kernel(
    const float* __restrict__ pred, const int* __restrict__ labels,
    const float* __restrict__ pos, float* __restrict__ out)
{
    __shared__ __align__(16) float SM[SMT];
    float* X1 = SM + O_X1;  float* X2 = SM + O_X2;  float* Qx = SM + O_QX;
    float* Y1 = SM + O_Y1;  float* Y2 = SM + O_Y2;  float* Qy = SM + O_QY;
    float* smx = SM + O_MX; float* sac = SM + O_AC;
    float* UY = SM + O_UY;  float* UX = SM + O_UX;
    float* YL = SM + O_YL;  float* YH = SM + O_YH;
    float* XL = SM + O_XL;  float* XH = SM + O_XH;
    float* s_l2b = SM + O_MS;  int* s_cnt = (int*)(SM + O_MS + 32);
    float* sred = SM + O_MS + 64;

    int tid = threadIdx.x, w = tid >> 5, lane = tid & 31;
    int b = blockIdx.x >> 5, cb = blockIdx.x & 31;
    int col0 = cb * 32, row0 = cb * 64;

    // ---- sort both sets by coord0 ----
    ull* xk = (ull*)(SM + O_X1);
    ull* yk = (ull*)(SM + O_Y1);
    const float2* pr2 = (const float2*)pred;
    const float2* po2 = (const float2*)pos;
    for (int i = tid; i < Pn; i += NT) yk[i] = ((ull)fkey(po2[b * Pn + i].x) << 32) | (unsigned)i;
    for (int i = tid; i < Sn; i += NT) xk[i] = ((ull)fkey(pr2[b * Sn + i].x) << 32) | (unsigned)i;
    bitonic(yk, Pn);
    bitonic(xk, Sn);
    ull myy[4], myx[8];
    #pragma unroll
    for (int t = 0; t < 4; t++) myy[t] = yk[tid + t * NT];
    #pragma unroll
    for (int t = 0; t < 8; t++) myx[t] = xk[tid + t * NT];
    __syncthreads();
    int* rk = (int*)(SM + O_QY);
    #pragma unroll
    for (int t = 0; t < 4; t++) {
        int i = tid + t * NT, idx = (int)(myy[t] & 0xFFFFFFFFu);
        float2 p = po2[b * Pn + idx];
        Y1[i] = SQI * p.x; Y2[i] = SQI * p.y; rk[idx] = i;
    }
    #pragma unroll
    for (int t = 0; t < 8; t++) {
        int i = tid + t * NT, idx = (int)(myx[t] & 0xFFFFFFFFu);
        float2 p = pr2[b * Sn + idx];
        X1[i] = 2.f * SQI * p.x; X2[i] = 2.f * SQI * p.y;
    }
    if (tid < 32) s_cnt[tid] = 0;
    __syncthreads();
    for (int s = tid; s < Sn; s += NT) {
        int rr = rk[labels[b * Sn + s]] - col0;
        if ((unsigned)rr < 32u) atomicAdd(&s_cnt[rr], 1);
    }
    __syncthreads();
    if (tid < 32) {
        int c = s_cnt[tid];
        s_l2b[tid] = (c > 0) ? lg2((float)c * (1.f / (float)Sn)) : NEG_BIG;
    }
    for (int i = tid; i < Pn; i += NT) Qy[i] = -(Y1[i] * Y1[i] + Y2[i] * Y2[i]);  // gs=0
    // chunk bounds (SQI units) + initial UY (gs=0 -> 0)
    if (tid < NCY) { YL[tid] = Y1[tid * 16]; YH[tid] = Y1[tid * 16 + 15]; UY[tid] = 0.f; }
    if (tid < NCX) { XL[tid] = 0.5f * X1[tid * 16]; XH[tid] = 0.5f * X1[tid * 16 + 15]; }
    unsigned ls = g_sns[b];
    __syncthreads();

    // per-lane constants
    int fr0 = row0 + lane, fr1 = fr0 + 32;
    float X1a = X1[fr0], X2a = X2[fr0], X1b = X1[fr1], X2b = X2[fr1];
    float xna = 0.25f * (X1a * X1a + X2a * X2a);
    float xnb = 0.25f * (X1b * X1b + X2b * X2b);
    ull X1A = pk(X1a, X1a), X2A = pk(X2a, X2a);
    ull X1B = pk(X1b, X1b), X2B = pk(X2b, X2b);
    int fj0a = min(max(lbound(Y1, Pn, 0.5f * X1a) - 8, 0), Pn - 16);
    int fj0b = min(max(lbound(Y1, Pn, 0.5f * X1b) - 8, 0), Pn - 16);
    float fxlo = 0.5f * X1[row0], fxhi = 0.5f * X1[row0 + 63];   // CTA row interval

    float Y1s = Y1[col0 + lane], Y2s = Y2[col0 + lane];
    float yn = Y1s * Y1s + Y2s * Y2s;
    ull Y1p = pk(Y1s, Y1s), Y2p = pk(Y2s, Y2s);
    int gj0 = min(max(lbound(X1, Sn, 2.f * Y1s) - 8, 0), Sn - 16);
    float gylo = Y1[col0], gyhi = Y1[col0 + 31];                 // CTA col interval

    for (int it = 0; it < ITERS; ++it) {
        // ---- f half: 64 rows (2/lane), 8 warps stride kept chunks ----
        {
            float La = -3e38f, Lb = -3e38f;
            #pragma unroll
            for (int j = 0; j < 16; j++) {
                La = fmaxf(La, fmaf(X1a, Y1[fj0a + j], fmaf(X2a, Y2[fj0a + j], Qy[fj0a + j])));
                Lb = fmaxf(Lb, fmaf(X1b, Y1[fj0b + j], fmaf(X2b, Y2[fj0b + j], Qy[fj0b + j])));
            }
            float thr = warp_min(fminf(La - xna, Lb - xnb)) - TH;
            int lo, hi;
            crange(UY, YL, YH, NCY, fxlo, fxhi, thr, lane, lo, hi);
            float m0 = -3e38f, m1 = -3e38f; ull a0 = 0ull, a1 = 0ull;
            for (int c = lo + w; c <= hi; c += 8) {
                const float *p1 = Y1 + c * 16, *p2 = Y2 + c * 16, *pq = Qy + c * 16;
                ull t0[8], t1[8];
                #pragma unroll
                for (int j = 0; j < 8; j++) {
                    ull y1 = *(const ull*)(p1 + 2 * j);
                    ull y2 = *(const ull*)(p2 + 2 * j);
                    ull q  = *(const ull*)(pq + 2 * j);
                    t0[j] = fma2(X1A, y1, fma2(X2A, y2, q));
                    t1[j] = fma2(X1B, y1, fma2(X2B, y2, q));
                }
                online8(t0, m0, a0);
                online8(t1, m1, a1);
            }
            smx[w * 64 + lane]      = m0;  sac[w * 64 + lane]      = hsum2(a0);
            smx[w * 64 + lane + 32] = m1;  sac[w * 64 + lane + 32] = hsum2(a1);
        }
        __syncthreads();
        if (tid < 64) {
            float M = -3e38f, A = 0.f;
            #pragma unroll
            for (int i = 0; i < 8; i++) M = fmaxf(M, smx[i * 64 + tid]);
            #pragma unroll
            for (int i = 0; i < 8; i++) A += sac[i * 64 + tid] * ex2(smx[i * 64 + tid] - M);
            int row = row0 + tid;
            float xnr = 0.25f * (X1[row] * X1[row] + X2[row] * X2[row]);
            g_fs[b * Sn + row] = -LOG2S - M - lg2(A) + xnr;
        }
        bat_bar(b, ls);
        for (int i = tid; i < Sn; i += NT)
            Qx[i] = __ldcg(&g_fs[b * Sn + i]) - 0.25f * (X1[i] * X1[i] + X2[i] * X2[i]);
        __syncthreads();
        if (tid < NCX) {
            float u = -3e38f;
            #pragma unroll
            for (int j = 0; j < 16; j++) {
                int i = tid * 16 + j;
                u = fmaxf(u, Qx[i] + 0.25f * (X1[i] * X1[i] + X2[i] * X2[i]));
            }
            UX[tid] = u;                                   // max fs per chunk
        }
        __syncthreads();

        // ---- g half: 32 cols (1/lane), 8 warps stride kept chunks ----
        {
            float Lg = -3e38f;
            #pragma unroll
            for (int j = 0; j < 16; j++)
                Lg = fmaxf(Lg, fmaf(Y1s, X1[gj0 + j], fmaf(Y2s, X2[gj0 + j], Qx[gj0 + j])));
            float thr = warp_min(Lg - yn) - TH;
            int lo, hi;
            crange(UX, XL, XH, NCX, gylo, gyhi, thr, lane, lo, hi);
            float m = -3e38f; ull acc = 0ull;
            for (int c = lo + w; c <= hi; c += 8) {
                const float *p1 = X1 + c * 16, *p2 = X2 + c * 16, *pq = Qx + c * 16;
                ull t[8];
                #pragma unroll
                for (int j = 0; j < 8; j++)
                    t[j] = fma2(Y1p, *(const ull*)(p1 + 2 * j),
                           fma2(Y2p, *(const ull*)(p2 + 2 * j), *(const ull*)(pq + 2 * j)));
                online8(t, m, acc);
            }
            smx[w * 64 + lane] = m; sac[w * 64 + lane] = hsum2(acc);
        }
        __syncthreads();
        if (tid < 32) {
            float M = -3e38f, A = 0.f;
            #pragma unroll
            for (int i = 0; i < 8; i++) M = fmaxf(M, smx[i * 64 + tid]);
            #pragma unroll
            for (int i = 0; i < 8; i++) A += sac[i * 64 + tid] * ex2(smx[i * 64 + tid] - M);
            float ynr = Y1[col0 + tid] * Y1[col0 + tid] + Y2[col0 + tid] * Y2[col0 + tid];
            g_gs[b * Pn + col0 + tid] = s_l2b[tid] - M - lg2(A) + ynr;
        }
        bat_bar(b, ls);
        for (int i = tid; i < Pn; i += NT)
            Qy[i] = __ldcg(&g_gs[b * Pn + i]) - (Y1[i] * Y1[i] + Y2[i] * Y2[i]);
        __syncthreads();
        if (tid < NCY) {
            float u = -3e38f;
            #pragma unroll
            for (int j = 0; j < 16; j++) {
                int i = tid * 16 + j;
                u = fmaxf(u, Qy[i] + (Y1[i] * Y1[i] + Y2[i] * Y2[i]));
            }
            UY[tid] = u;                                   // max gs per chunk
        }
        __syncthreads();
    }

    // ---- final transport distance ----
    {
        float La = -3e38f, Lb = -3e38f;
        #pragma unroll
        for (int j = 0; j < 16; j++) {
            La = fmaxf(La, fmaf(X1a, Y1[fj0a + j], fmaf(X2a, Y2[fj0a + j], Qy[fj0a + j])));
            Lb = fmaxf(Lb, fmaf(X1b, Y1[fj0b + j], fmaf(X2b, Y2[fj0b + j], Qy[fj0b + j])));
        }
        float thr = warp_min(fminf(La - xna, Lb - xnb)) - TH;
        int lo, hi;
        crange(UY, YL, YH, NCY, fxlo, fxhi, thr, lane, lo, hi);
        float q0 = Qx[fr0], q1 = Qx[fr1];
        float acc = 0.f;
        for (int c = lo + w; c <= hi; c += 8) {
            const float *p1 = Y1 + c * 16, *p2 = Y2 + c * 16, *pq = Qy + c * 16;
            #pragma unroll
            for (int j = 0; j < 8; j++) {
                ull y1 = *(const ull*)(p1 + 2 * j);
                ull y2 = *(const ull*)(p2 + 2 * j);
                ull qp = *(const ull*)(pq + 2 * j);
                ull t0 = fma2(X1A, y1, fma2(X2A, y2, qp));
                ull t1 = fma2(X1B, y1, fma2(X2B, y2, qp));
                float qa, qb, y1a, y1b, y2a, y2b, t0a, t0b, t1a, t1b;
                upk(qp, qa, qb); upk(y1, y1a, y1b); upk(y2, y2a, y2b);
                upk(t0, t0a, t0b); upk(t1, t1a, t1b);
                float yna2 = y1a * y1a + y2a * y2a, ynb2 = y1b * y1b + y2b * y2b;
                acc = fmaf(ex2(t0a + q0), qa + yna2 + xna - t0a, acc);
                acc = fmaf(ex2(t0b + q0), qb + ynb2 + xna - t0b, acc);
                acc = fmaf(ex2(t1a + q1), qa + yna2 + xnb - t1a, acc);
                acc = fmaf(ex2(t1b + q1), qb + ynb2 + xnb - t1b, acc);
            }
        }
        acc = warp_sum(acc);
        if (lane == 0) sred[w] = acc;
    }
    __syncthreads();
    if (tid == 0) {
        float s = 0.f;
        #pragma unroll
        for (int i = 0; i < 8; i++) s += sred[i];
        g_part[blockIdx.x] = s;
    }

    // ---- grid-wide deterministic reduce ----
    __threadfence();
    __syncthreads();
    if (blockIdx.x == 0) {
        if (tid == 0) {
            atomicAdd(&g_gcnt, 1u);
            while (*((volatile unsigned*)&g_gcnt) < (unsigned)GRID) { }
            __threadfence();
        }
        __syncthreads();
        smx[tid] = __ldcg(&g_part[tid]);
        __syncthreads();
        #pragma unroll
        for (int o = 128; o; o >>= 1) {
            if (tid < o) smx[tid] += smx[tid + o];
            __syncthreads();
        }
        if (tid == 0) {
            out[0] = smx[0] * (1.f / (IL2 * (float)Bn));
            g_gcnt = 0;
        }
    } else {
        if (tid == 0) atomicAdd(&g_gcnt, 1u);
    }
}

extern "C" void kernel_launch(void* const* d_in, const int* in_sizes, int n_in,
                              void* d_out, int out_size) {
    const float* pred   = (const float*)d_in[0];
    const int*   labels = (const int*)d_in[1];
    const float* pos    = (const float*)d_in[2];
    float*       out    = (float*)d_out;

    sinkhorn_kernel<<<GRID, NT>>>(pred, labels, pos, out);
}

// round 8
// speedup vs baseline: 1.4185x; 1.3204x over previous
#include <cuda_runtime.h>
typedef unsigned long long ull;

constexpr int Bn = 8, Sn = 2048, Pn = 1024, ITERS = 50;
constexpr int CPB = 32, GRID = Bn * CPB, NT = 256;

constexpr float SQI   = 12.011224081528898f;   // sqrt((1/eps)*log2 e)
constexpr float IL2   = 144.26950408889634f;
constexpr float LOG2S = 11.0f;
constexpr float CL    = 80.f;                  // clamp headroom above R

__device__ float g_fs[Bn * Sn], g_gs[Bn * Pn], g_part[GRID];
__device__ unsigned g_cnt[Bn];
__device__ unsigned g_sns[Bn];
__device__ unsigned g_gcnt;

__device__ __forceinline__ float ex2(float x) { float r; asm("ex2.approx.f32 %0, %1;" : "=f"(r) : "f"(x)); return r; }
__device__ __forceinline__ float lg2(float x) { float r; asm("lg2.approx.f32 %0, %1;" : "=f"(r) : "f"(x)); return r; }
__device__ __forceinline__ ull pk(float lo, float hi) { ull r; asm("mov.b64 %0, {%1, %2};" : "=l"(r) : "f"(lo), "f"(hi)); return r; }
__device__ __forceinline__ void upk(ull p, float& a, float& b) { asm("mov.b64 {%0, %1}, %2;" : "=f"(a), "=f"(b) : "l"(p)); }
__device__ __forceinline__ ull add2(ull a, ull b) { ull r; asm("add.rn.f32x2 %0, %1, %2;" : "=l"(r) : "l"(a), "l"(b)); return r; }
__device__ __forceinline__ ull fma2(ull a, ull b, ull c) { ull r; asm("fma.rn.f32x2 %0, %1, %2, %3;" : "=l"(r) : "l"(a), "l"(b), "l"(c)); return r; }
__device__ __forceinline__ float warp_sum(float a) {
    #pragma unroll
    for (int o = 16; o; o >>= 1) a += __shfl_xor_sync(0xffffffffu, a, o);
    return a;
}

// per-batch barrier: CG-style release arrive + acquire spin (all CTAs co-resident)
__device__ __forceinline__ void bat_bar(int b, unsigned& ls) {
    ls ^= 1u;
    __syncthreads();
    if (threadIdx.x == 0) {
        unsigned old;
        asm volatile("atom.acq_rel.gpu.add.u32 %0,[%1],%2;"
                     : "=r"(old) : "l"(&g_cnt[b]), "r"(1u) : "memory");
        if (old == CPB - 1) {
            g_cnt[b] = 0;
            asm volatile("st.release.gpu.u32 [%0],%1;" :: "l"(&g_sns[b]), "r"(ls) : "memory");
        } else {
            unsigned v;
            do { asm volatile("ld.acquire.gpu.u32 %0,[%1];" : "=r"(v) : "l"(&g_sns[b]) : "memory"); }
            while (v != ls);
        }
    }
    __syncthreads();
}

__global__ void __launch_bounds__(NT, 2) sinkhorn_kernel(
    const float* __restrict__ pred, const int* __restrict__ labels,
    const float* __restrict__ pos, float* __restrict__ out)
{
    __shared__ __align__(16) float X1[Sn], X2[Sn], Qx[Sn];
    __shared__ __align__(16) float Y1c[Pn], Y2c[Pn], Qyc[Pn], l2bC[Pn];
    __shared__ float sA[512], sRf[64], sRg[32], sred[8];
    __shared__ int swp[8], sPvA[1];

    int tid = threadIdx.x, w = tid >> 5, lane = tid & 31;
    int b = blockIdx.x >> 5, cb = blockIdx.x & 31;
    int row0 = cb * 64;

    // ---- stage X (prescaled by 2*SQI) ----
    const float2* pr2 = (const float2*)pred + b * Sn;
    for (int i = tid; i < Sn; i += NT) {
        float2 p = pr2[i];
        X1[i] = 2.f * SQI * p.x;  X2[i] = 2.f * SQI * p.y;
    }
    // ---- histogram (overlay in Qx region) ----
    int* hist = (int*)Qx;
    for (int i = tid; i < Pn; i += NT) hist[i] = 0;
    __syncthreads();
    const int* lab = labels + b * Sn;
    for (int s = tid; s < Sn; s += NT) atomicAdd(&hist[lab[s]], 1);
    __syncthreads();
    // ---- compact nonzero-weight positions (deterministic prefix scan) ----
    int c4[4], tsum = 0;
    #pragma unroll
    for (int k = 0; k < 4; k++) { c4[k] = hist[tid * 4 + k] > 0; tsum += c4[k]; }
    int pre = tsum;
    #pragma unroll
    for (int o = 1; o < 32; o <<= 1) { int v = __shfl_up_sync(~0u, pre, o); if (lane >= o) pre += v; }
    if (lane == 31) swp[w] = pre;
    __syncthreads();
    if (tid == 0) { int r = 0; for (int i = 0; i < 8; i++) { int v = swp[i]; swp[i] = r; r += v; } sPvA[0] = r; }
    __syncthreads();
    int Pv = sPvA[0];
    int off = swp[w] + pre - tsum;
    const float2* po2 = (const float2*)pos + b * Pn;
    #pragma unroll
    for (int k = 0; k < 4; k++) {
        if (c4[k]) {
            int p = tid * 4 + k;
            float2 yy = po2[p];
            Y1c[off] = SQI * yy.x;  Y2c[off] = SQI * yy.y;
            l2bC[off] = lg2((float)hist[p] * (1.f / (float)Sn));
            off++;
        }
    }
    __syncthreads();   // hist done; Qx region free until first restage
    int PvPad = (Pv + 15) & ~15;
    for (int i = tid; i < Pn; i += NT) {
        if (i < Pv) Qyc[i] = -(Y1c[i] * Y1c[i] + Y2c[i] * Y2c[i]);   // G=0 -> Qy=-yn
        else { Qyc[i] = -1e30f; Y1c[i] = 0.f; Y2c[i] = 0.f; l2bC[i] = 0.f; }
    }
    unsigned ls = g_sns[b];
    __syncthreads();

    // per-lane constants
    int fr0 = row0 + lane, fr1 = fr0 + 32;
    float X1a = X1[fr0], X2a = X2[fr0], X1b_ = X1[fr1], X2b_ = X2[fr1];
    ull X1A = pk(X1a, X1a), X2A = pk(X2a, X2a);
    ull X1B = pk(X1b_, X1b_), X2B = pk(X2b_, X2b_);
    int cpc = (Pv + CPB - 1) / CPB;
    int myc0 = cb * cpc;
    int myn = min(cpc, max(0, Pv - myc0));
    int gcol = myc0 + ((lane < myn) ? lane : 0);
    float Y1s = Y1c[gcol], Y2s = Y2c[gcol];
    ull Y1p = pk(Y1s, Y1s), Y2p = pk(Y2s, Y2s);
    int nch = PvPad >> 4;

    for (int it = 0; it < ITERS; ++it) {
        // ================= f half =================
        if (it == 0) {   // seed R: exact row max (fma-only pass)
            float m0 = -3e38f, m1 = -3e38f;
            for (int c = w; c < nch; c += 8) {
                const ull* y1 = (const ull*)(Y1c + c * 16);
                const ull* y2 = (const ull*)(Y2c + c * 16);
                const ull* qq = (const ull*)(Qyc + c * 16);
                #pragma unroll
                for (int j = 0; j < 8; j++) {
                    ull t0 = fma2(X1A, y1[j], fma2(X2A, y2[j], qq[j]));
                    ull t1 = fma2(X1B, y1[j], fma2(X2B, y2[j], qq[j]));
                    float a, b2; upk(t0, a, b2); m0 = fmaxf(m0, fmaxf(a, b2));
                    upk(t1, a, b2); m1 = fmaxf(m1, fmaxf(a, b2));
                }
            }
            sA[w * 64 + lane] = m0;  sA[w * 64 + lane + 32] = m1;
            __syncthreads();
            if (tid < 64) {
                float M = -3e38f;
                #pragma unroll
                for (int i = 0; i < 8; i++) M = fmaxf(M, sA[i * 64 + tid]);
                sRf[tid] = M;
            }
            __syncthreads();
        }
        {
            float R0 = sRf[lane], R1 = sRf[lane + 32];
            ull nR0 = pk(-R0, -R0), nR1 = pk(-R1, -R1);
            float a0 = 0.f, a1 = 0.f, a2 = 0.f, a3 = 0.f;
            for (int c = w; c < nch; c += 8) {
                const ull* y1 = (const ull*)(Y1c + c * 16);
                const ull* y2 = (const ull*)(Y2c + c * 16);
                const ull* qq = (const ull*)(Qyc + c * 16);
                #pragma unroll
                for (int j = 0; j < 8; j++) {
                    ull ly1 = y1[j], ly2 = y2[j], q = qq[j];
                    ull t0 = add2(fma2(X1A, ly1, fma2(X2A, ly2, q)), nR0);
                    ull t1 = add2(fma2(X1B, ly1, fma2(X2B, ly2, q)), nR1);
                    float ta, tb; upk(t0, ta, tb);
                    a0 = fmaf(ex2(fminf(ta, CL)), 1.f, a0);
                    a1 = fmaf(ex2(fminf(tb, CL)), 1.f, a1);
                    upk(t1, ta, tb);
                    a2 = fmaf(ex2(fminf(ta, CL)), 1.f, a2);
                    a3 = fmaf(ex2(fminf(tb, CL)), 1.f, a3);
                }
            }
            sA[w * 64 + lane] = a0 + a1;  sA[w * 64 + lane + 32] = a2 + a3;
        }
        __syncthreads();
        if (tid < 64) {
            float A = 0.f;
            #pragma unroll
            for (int i = 0; i < 8; i++) A += sA[i * 64 + tid];
            A = fmaxf(A, 1e-30f);
            float Lse = sRf[tid] + lg2(A);
            sRf[tid] = Lse;
            g_fs[b * Sn + row0 + tid] = -LOG2S - Lse;    // Qx-form directly
        }
        bat_bar(b, ls);
        for (int i = tid; i < Sn; i += NT) Qx[i] = __ldcg(&g_fs[b * Sn + i]);
        __syncthreads();

        // ================= g half =================
        if (it == 0) {
            float m = -3e38f;
            int base = w * 128;
            for (int c = 0; c < 16; c++) {
                const ull* x1 = (const ull*)(X1 + (base + c * 8) * 2);
                const ull* x2 = (const ull*)(X2 + (base + c * 8) * 2);
                const ull* qq = (const ull*)(Qx + (base + c * 8) * 2);
                #pragma unroll
                for (int j = 0; j < 8; j++) {
                    ull t = fma2(Y1p, x1[j], fma2(Y2p, x2[j], qq[j]));
                    float a, b2; upk(t, a, b2);
                    m = fmaxf(m, fmaxf(a, b2));
                }
            }
            sA[w * 64 + lane] = m;
            __syncthreads();
            if (tid < 32) {
                float M = -3e38f;
                #pragma unroll
                for (int i = 0; i < 8; i++) M = fmaxf(M, sA[i * 64 + tid]);
                sRg[tid] = M;
            }
            __syncthreads();
        }
        {
            float Rg = sRg[lane];
            ull nR = pk(-Rg, -Rg);
            float a0 = 0.f, a1 = 0.f;
            int base = w * 128;
            for (int c = 0; c < 16; c++) {
                const ull* x1 = (const ull*)(X1 + (base + c * 8) * 2);
                const ull* x2 = (const ull*)(X2 + (base + c * 8) * 2);
                const ull* qq = (const ull*)(Qx + (base + c * 8) * 2);
                #pragma unroll
                for (int j = 0; j < 8; j++) {
                    ull t = add2(fma2(Y1p, x1[j], fma2(Y2p, x2[j], qq[j])), nR);
                    float ta, tb; upk(t, ta, tb);
                    a0 = fmaf(ex2(fminf(ta, CL)), 1.f, a0);
                    a1 = fmaf(ex2(fminf(tb, CL)), 1.f, a1);
                }
            }
            sA[w * 64 + lane] = a0 + a1;
        }
        __syncthreads();
        if (tid < 32) {
            float A = 0.f;
            #pragma unroll
            for (int i = 0; i < 8; i++) A += sA[i * 64 + tid];
            A = fmaxf(A, 1e-30f);
            float Lse = sRg[tid] + lg2(A);
            sRg[tid] = Lse;
            if (tid < myn) g_gs[b * Pn + myc0 + tid] = l2bC[myc0 + tid] - Lse;  // Qy-form
        }
        bat_bar(b, ls);
        for (int i = tid; i < Pv; i += NT) Qyc[i] = __ldcg(&g_gs[b * Pn + i]);
        __syncthreads();
    }

    // ================= final transport distance =================
    {
        float q0 = Qx[fr0], q1 = Qx[fr1];
        float xna = 0.25f * (X1a * X1a + X2a * X2a);
        float xnb = 0.25f * (X1b_ * X1b_ + X2b_ * X2b_);
        float acc = 0.f;
        for (int c = w; c < nch; c += 8) {
            const ull* y1 = (const ull*)(Y1c + c * 16);
            const ull* y2 = (const ull*)(Y2c + c * 16);
            const ull* qq = (const ull*)(Qyc + c * 16);
            #pragma unroll
            for (int j = 0; j < 8; j++) {
                ull ly1 = y1[j], ly2 = y2[j], q = qq[j];
                ull t0 = fma2(X1A, ly1, fma2(X2A, ly2, q));
                ull t1 = fma2(X1B, ly1, fma2(X2B, ly2, q));
                float qa, qb, y1a, y1b, y2a, y2b, t0a, t0b, t1a, t1b;
                upk(q, qa, qb); upk(ly1, y1a, y1b); upk(ly2, y2a, y2b);
                upk(t0, t0a, t0b); upk(t1, t1a, t1b);
                float yna2 = y1a * y1a + y2a * y2a, ynb2 = y1b * y1b + y2b * y2b;
                acc = fmaf(ex2(fminf(t0a + q0, CL)), qa + yna2 + xna - t0a, acc);
                acc = fmaf(ex2(fminf(t0b + q0, CL)), qb + ynb2 + xna - t0b, acc);
                acc = fmaf(ex2(fminf(t1a + q1, CL)), qa + yna2 + xnb - t1a, acc);
                acc = fmaf(ex2(fminf(t1b + q1, CL)), qb + ynb2 + xnb - t1b, acc);
            }
        }
        acc = warp_sum(acc);
        if (lane == 0) sred[w] = acc;
    }
    __syncthreads();
    if (tid == 0) {
        float s = 0.f;
        #pragma unroll
        for (int i = 0; i < 8; i++) s += sred[i];
        g_part[blockIdx.x] = s;
    }

    // ---- grid-wide deterministic reduce ----
    __threadfence();
    __syncthreads();
    if (blockIdx.x == 0) {
        if (tid == 0) {
            atomicAdd(&g_gcnt, 1u);
            while (*((volatile unsigned*)&g_gcnt) < (unsigned)GRID) { }
            __threadfence();
        }
        __syncthreads();
        sA[tid] = __ldcg(&g_part[tid]);
        __syncthreads();
        #pragma unroll
        for (int o = 128; o; o >>= 1) {
            if (tid < o) sA[tid] += sA[tid + o];
            __syncthreads();
        }
        if (tid == 0) {
            out[0] = sA[0] * (1.f / (IL2 * (float)Bn));
            g_gcnt = 0;
        }
    } else {
        if (tid == 0) atomicAdd(&g_gcnt, 1u);
    }
}

extern "C" void kernel_launch(void* const* d_in, const int* in_sizes, int n_in,
                              void* d_out, int out_size) {
    const float* pred   = (const float*)d_in[0];
    const int*   labels = (const int*)d_in[1];
    const float* pos    = (const float*)d_in[2];
    float*       out    = (float*)d_out;

    sinkhorn_kernel<<<GRID, NT>>>(pred, labels, pos, out);
}